// round 11
// baseline (speedup 1.0000x reference)
#include <cuda_runtime.h>
#include <cuda_fp16.h>
#include <math.h>
#include <stdint.h>

// Problem constants
#define Bb   4
#define Cc   64
#define Hh   96
#define Ww   96
#define HW   (Hh*Ww)            // 9216
#define Oo   64
#define CIN3 (3*Cc)             // 192
#define IMG  (Cc*HW)            // 589824
#define NPIX (Bb*HW)            // 36864
#define NCH  27                 // K chunks of 64: K = k*192 + c (k-major)
#define NTOT (Bb*CIN3*HW)       // 7077888
#define XPAD 256
#define NOUT (Bb*Oo*HW)         // 2359296

// Scratch
__device__ float4 g_mw[Bb * 9 * HW];
__device__ int    g_me[Bb * 9 * HW];
__device__ __half g_xn_raw[NTOT + 2 * XPAD];
__device__ __half g_xs_raw[NTOT + 2 * XPAD];
__device__ __half g_wh[NCH * 64 * 64];
__device__ float  g_part[2 * NOUT];            // split-K partials

// ---------------- helpers ----------------
__device__ __forceinline__ uint32_t smem_to_u32(const void* p) {
    uint32_t a;
    asm("{ .reg .u64 t; cvta.to.shared.u64 t, %1; cvt.u32.u64 %0, t; }"
        : "=r"(a) : "l"(p));
    return a;
}
__device__ __forceinline__ void ldsm_x4(uint32_t* r, uint32_t addr) {
    asm volatile("ldmatrix.sync.aligned.m8n8.x4.shared.b16 {%0,%1,%2,%3}, [%4];"
        : "=r"(r[0]), "=r"(r[1]), "=r"(r[2]), "=r"(r[3]) : "r"(addr));
}
__device__ __forceinline__ void mma_f16(float* d, const uint32_t* a,
                                        uint32_t b0, uint32_t b1) {
    asm volatile("mma.sync.aligned.m16n8k16.row.col.f32.f16.f16.f32 "
        "{%0,%1,%2,%3}, {%4,%5,%6,%7}, {%8,%9}, {%0,%1,%2,%3};"
        : "+f"(d[0]), "+f"(d[1]), "+f"(d[2]), "+f"(d[3])
        : "r"(a[0]), "r"(a[1]), "r"(a[2]), "r"(a[3]), "r"(b0), "r"(b1));
}
__device__ __forceinline__ void cp_async16(uint32_t smem_addr, const void* gptr) {
    asm volatile("cp.async.cg.shared.global [%0], [%1], 16;"
        :: "r"(smem_addr), "l"(gptr));
}
#define CP_COMMIT() asm volatile("cp.async.commit_group;" ::: "memory")
#define CP_WAIT0()  asm volatile("cp.async.wait_group 0;" ::: "memory")

// ---------------------------------------------------------------------------
// Prolog: concurrent block-range dispatch (256 threads)
//   [0,144):     offset conv3x3 + bilinear meta (256 px/block)
//   [144,576):   weight prep (432 blocks)
//   [576,4032):  diff + fp16 repack, 8 elems/thread (3456 blocks)
// ---------------------------------------------------------------------------
__global__ __launch_bounds__(256) void prolog_kernel(
        const float* __restrict__ ref, const float* __restrict__ dist,
        const float* __restrict__ ow, const float* __restrict__ ob,
        const float* __restrict__ dw,
        float* __restrict__ out_diff,
        __half* __restrict__ xn, __half* __restrict__ xs,
        float4* __restrict__ mw, int* __restrict__ me,
        __half* __restrict__ wh) {
    __shared__ __align__(16) float s_w[576 * 20];
    int tid = threadIdx.x;
    int bid = blockIdx.x;

    if (bid >= 576) {
        // ---- repack: 8 elems/thread ----
        int base = (bid - 576) * 2048 + tid;
#pragma unroll
        for (int it = 0; it < 8; it++) {
            int i = base + it * 256;
            int b = i / (CIN3 * HW);
            int r = i - b * (CIN3 * HW);
            int c = r / HW;
            int e = r - c * HW;
            float v;
            if (c < Cc) {
                v = __ldg(ref + (b * Cc + c) * HW + e);
            } else if (c < 2 * Cc) {
                v = __ldg(dist + (b * Cc + (c - Cc)) * HW + e);
            } else {
                int cc = c - 2 * Cc;
                float rr = __ldg(ref  + (b * Cc + cc) * HW + e);
                float dd = __ldg(dist + (b * Cc + cc) * HW + e);
                v = (rr - dd) * (rr - dd);
                out_diff[(b * Cc + cc) * HW + e] = v;
            }
            __half h = __float2half_rn(v);
            xn[i] = h;
            if (i > 0) xs[i - 1] = h;
        }
        return;
    }
    if (bid >= 144) {
        // ---- wprep ----
        int i = (bid - 144) * 256 + tid;
        int c  = i & 63;
        int o  = (i >> 6) & 63;
        int ch = i >> 12;
        int k  = ch / 3;
        int cg = (ch % 3) * 64 + c;
        float v = __ldg(dw + o * (CIN3 * 9) + cg * 9 + k);
        int elem = o * 64 + (((c >> 3) ^ (o & 7)) << 3) + (c & 7);
        wh[ch * 4096 + elem] = __float2half_rn(v);
        return;
    }

    // ---- offset conv + meta ----
    for (int i = tid; i < 18 * 576; i += 256) {
        int o = i / 576, ck = i % 576;
        s_w[ck * 20 + o] = ow[i];
    }
    __syncthreads();

    int p = bid * 256 + tid;
    int b = p / HW;
    int pix = p % HW;
    int y = pix / Ww, x = pix % Ww;

    int  idx9[9]; bool ok9[9];
#pragma unroll
    for (int ky = 0; ky < 3; ky++)
#pragma unroll
        for (int kx = 0; kx < 3; kx++) {
            int yy = y + ky - 1, xx = x + kx - 1;
            bool ok = (yy >= 0) && (yy < Hh) && (xx >= 0) && (xx < Ww);
            ok9[ky * 3 + kx] = ok;
            idx9[ky * 3 + kx] = (ok ? yy : 0) * Ww + (ok ? xx : 0);
        }

    float acc[18];
#pragma unroll
    for (int o = 0; o < 18; o++) acc[o] = 0.f;

    const float* xb = ref + b * IMG;
    for (int c = 0; c < Cc; c++) {
        const float* xc = xb + c * HW;
#pragma unroll
        for (int k = 0; k < 9; k++) {
            float v = ok9[k] ? __ldg(xc + idx9[k]) : 0.f;
            int base = (c * 9 + k) * 20;
            float4 w0 = *(const float4*)&s_w[base];
            float4 w1 = *(const float4*)&s_w[base + 4];
            float4 w2 = *(const float4*)&s_w[base + 8];
            float4 w3 = *(const float4*)&s_w[base + 12];
            float  wa = s_w[base + 16];
            float  wb = s_w[base + 17];
            acc[0]  += v * w0.x;  acc[1]  += v * w0.y;  acc[2]  += v * w0.z;  acc[3]  += v * w0.w;
            acc[4]  += v * w1.x;  acc[5]  += v * w1.y;  acc[6]  += v * w1.z;  acc[7]  += v * w1.w;
            acc[8]  += v * w2.x;  acc[9]  += v * w2.y;  acc[10] += v * w2.z;  acc[11] += v * w2.w;
            acc[12] += v * w3.x;  acc[13] += v * w3.y;  acc[14] += v * w3.z;  acc[15] += v * w3.w;
            acc[16] += v * wa;    acc[17] += v * wb;
        }
    }

#pragma unroll
    for (int k = 0; k < 9; k++) {
        float offy = acc[2 * k]     + __ldg(ob + 2 * k);
        float offx = acc[2 * k + 1] + __ldg(ob + 2 * k + 1);
        float py = (float)(y - 1 + k / 3) + offy;
        float px = (float)(x - 1 + k % 3) + offx;
        float fy = floorf(py), fx = floorf(px);
        int y0 = (int)fy, x0 = (int)fx;
        float dy = py - fy, dx = px - fx;
        float wv[4];
#pragma unroll
        for (int t = 0; t < 4; t++) {
            int yt = y0 + (t >> 1);
            int xt = x0 + (t & 1);
            float wt = ((t >> 1) ? dy : (1.f - dy)) * ((t & 1) ? dx : (1.f - dx));
            bool valid = (yt >= 0) && (yt < Hh) && (xt >= 0) && (xt < Ww);
            wv[t] = valid ? wt : 0.f;
        }
        int y0c = y0 < -1 ? -1 : (y0 > Hh ? Hh : y0);
        int x0c = x0 < -1 ? -1 : (x0 > Ww ? Ww : x0);
        int e0 = y0c * Ww + x0c;
        int mo = (b * 9 + k) * HW + pix;
        mw[mo] = make_float4(wv[0], wv[1], wv[2], wv[3]);
        me[mo] = e0;
    }
}

// ---------------------------------------------------------------------------
// Deform (split-K x2): block = M64 x N64, 256 thr (8 warps, warp tile 16x32),
// s = bid&1 selects chunks [0,14) or [14,27). Partials (fp32) to g_part.
// Per buffer (16KB): A@0 8K | B@8K 8K. 4 blocks/SM target.
// ---------------------------------------------------------------------------
#define SM_BUF   16384
#define SM_AHOF  0
#define SM_BHOF  8192
#define SM_TOTAL (2 * SM_BUF)

__global__ __launch_bounds__(256, 4) void deform_kernel(
        const __half* __restrict__ xn, const __half* __restrict__ xs,
        const float4* __restrict__ mw, const int* __restrict__ me,
        const __half* __restrict__ wh,
        float* __restrict__ part) {
    extern __shared__ char smem[];
    uint32_t sb = smem_to_u32(smem);

    int tid  = threadIdx.x;
    int lane = tid & 31;
    int warp = tid >> 5;
    int bid  = blockIdx.x;
    int s    = bid & 1;
    int tile = bid >> 1;
    int b    = tile / 144;
    int pix0 = (tile % 144) * 64;

    int ch0 = s ? 14 : 0;
    int ch1 = s ? 27 : 14;

    int p  = tid & 63;          // pixel
    int cq = tid >> 6;          // channel quarter (16 ch)
    uint32_t a_sts = (uint32_t)p * 128;

    int m0 = (warp & 3) * 16;
    int n0 = (warp >> 2) * 32;

    float acc[4][4];
#pragma unroll
    for (int j = 0; j < 4; j++)
#pragma unroll
        for (int q = 0; q < 4; q++) acc[j][q] = 0.f;

    uint32_t a_m  = lane & 15;
    uint32_t a_kc = lane >> 4;
    uint32_t b_n  = ((lane >> 4) << 3) + (lane & 7);
    uint32_t b_kc = (lane >> 3) & 1;

    // build one 8-channel group g2 (0/1) of chunk ch
    auto build_g = [&](int ch, int g2, __half2 wtop, __half2 wbot,
                       const __half2* srcp) {
        char* bufc = smem + (ch & 1) * SM_BUF;
        __half v[8];
#pragma unroll
        for (int j = 0; j < 8; j++) {
            const __half2* pl = srcp + (g2 * 8 + j) * (HW / 2);
            __half2 a  = __ldg(pl);
            __half2 bb = __ldg(pl + (Ww / 2));
            __half2 t  = __hfma2(wbot, bb, __hmul2(wtop, a));
            v[j] = __hadd(__low2half(t), __high2half(t));
        }
        uint32_t hp[4];
#pragma unroll
        for (int jj = 0; jj < 4; jj++) {
            __half2 hb = __halves2half2(v[2 * jj], v[2 * jj + 1]);
            hp[jj] = *(uint32_t*)&hb;
        }
        int kc = cq * 2 + g2;
        uint32_t off = a_sts + (uint32_t)((kc ^ (p & 7)) << 4);
        *(uint4*)(bufc + SM_AHOF + off) = make_uint4(hp[0], hp[1], hp[2], hp[3]);
    };

    auto chunk_meta = [&](int ch, __half2& wtop, __half2& wbot,
                          const __half2*& srcp) {
        int k   = ch / 3;
        int cbl = ch - 3 * k;
        float4 w = __ldg(mw + (b * 9 + k) * HW + pix0 + p);
        int   e0 = __ldg(me + (b * 9 + k) * HW + pix0 + p);
        wtop = __floats2half2_rn(w.x, w.y);
        wbot = __floats2half2_rn(w.z, w.w);
        int sel = e0 & 1;
        int h2base = (e0 - sel) >> 1;
        const __half* base = sel ? xs : xn;
        srcp = (const __half2*)base
             + (size_t)(b * CIN3 + cbl * 64 + cq * 16) * (HW / 2)
             + h2base;
    };

    auto stage_B = [&](int ch) {
        uint32_t bufb = sb + (ch & 1) * SM_BUF;
        const char* gh = (const char*)(wh + ch * 4096);
        cp_async16(bufb + SM_BHOF + tid * 16, gh + tid * 16);
        cp_async16(bufb + SM_BHOF + (tid + 256) * 16, gh + (tid + 256) * 16);
        CP_COMMIT();
    };

    // prologue: first chunk
    stage_B(ch0);
    {
        __half2 wtop, wbot; const __half2* srcp;
        chunk_meta(ch0, wtop, wbot, srcp);
        build_g(ch0, 0, wtop, wbot, srcp);
        build_g(ch0, 1, wtop, wbot, srcp);
    }
    CP_WAIT0();
    __syncthreads();

    for (int ch = ch0; ch < ch1; ch++) {
        int nxt = ch + 1;
        bool has_nxt = (nxt < ch1);
        if (has_nxt) stage_B(nxt);

        __half2 nwt = __float2half2_rn(0.f), nwb = __float2half2_rn(0.f);
        const __half2* nsrc = (const __half2*)xn;
        if (has_nxt) chunk_meta(nxt, nwt, nwb, nsrc);

        uint32_t bufb = sb + (ch & 1) * SM_BUF;
#pragma unroll
        for (int ks = 0; ks < 4; ks++) {
            uint32_t ah[4], bh[2][4];
            {
                uint32_t row = m0 + a_m;
                uint32_t aoff = row * 128 + ((((ks << 1) + a_kc) ^ (row & 7)) << 4);
                ldsm_x4(ah, bufb + SM_AHOF + aoff);
            }
#pragma unroll
            for (int g = 0; g < 2; g++) {
                uint32_t n  = n0 + g * 16 + b_n;
                uint32_t kc = (ks << 1) + b_kc;
                uint32_t boff = n * 128 + ((kc ^ (n & 7)) << 4);
                ldsm_x4(bh[g], bufb + SM_BHOF + boff);
            }
#pragma unroll
            for (int g = 0; g < 2; g++)
#pragma unroll
                for (int s2 = 0; s2 < 2; s2++) {
                    int ni = g * 2 + s2;
                    mma_f16(acc[ni], ah, bh[g][2 * s2], bh[g][2 * s2 + 1]);
                }
            if (has_nxt && (ks == 0 || ks == 2))
                build_g(nxt, ks >> 1, nwt, nwb, nsrc);
        }

        CP_WAIT0();
        __syncthreads();
    }

    // epilogue: store fp32 partials (no bias/relu)
    float* pp = part + (size_t)s * NOUT;
    int r  = lane >> 2;
    int cp = (lane & 3) * 2;
    int pixb = pix0 + m0 + r;
#pragma unroll
    for (int ni = 0; ni < 4; ni++) {
        int o = n0 + ni * 8 + cp;
        float* o0 = pp + (size_t)(b * Oo + o) * HW;
        float* o1 = pp + (size_t)(b * Oo + o + 1) * HW;
        o0[pixb]     = acc[ni][0];
        o1[pixb]     = acc[ni][1];
        o0[pixb + 8] = acc[ni][2];
        o1[pixb + 8] = acc[ni][3];
    }
}

// ---------------------------------------------------------------------------
// Reduce: out = relu(p0 + p1 + bias)
// ---------------------------------------------------------------------------
__global__ __launch_bounds__(256) void reduce_kernel(
        const float4* __restrict__ part, const float* __restrict__ db,
        float4* __restrict__ out) {
    int i4 = blockIdx.x * 256 + threadIdx.x;
    if (i4 >= NOUT / 4) return;
    float4 p0 = __ldg(part + i4);
    float4 p1 = __ldg(part + NOUT / 4 + i4);
    int o = (i4 / (HW / 4)) % Oo;
    float bias = __ldg(db + o);
    float4 v;
    v.x = fmaxf(p0.x + p1.x + bias, 0.f);
    v.y = fmaxf(p0.y + p1.y + bias, 0.f);
    v.z = fmaxf(p0.z + p1.z + bias, 0.f);
    v.w = fmaxf(p0.w + p1.w + bias, 0.f);
    out[i4] = v;
}

// ---------------------------------------------------------------------------
extern "C" void kernel_launch(void* const* d_in, const int* in_sizes, int n_in,
                              void* d_out, int out_size) {
    const float* ref  = (const float*)d_in[0];
    const float* dist = (const float*)d_in[1];
    const float* ow   = (const float*)d_in[2];
    const float* ob   = (const float*)d_in[3];
    const float* dw   = (const float*)d_in[4];
    const float* db   = (const float*)d_in[5];
    float* out = (float*)d_out;
    float* out_feat = out;
    float* out_diff = out + Bb * IMG;

    float4* mw;  cudaGetSymbolAddress((void**)&mw, g_mw);
    int*    me;  cudaGetSymbolAddress((void**)&me, g_me);
    __half* xnr; cudaGetSymbolAddress((void**)&xnr, g_xn_raw);
    __half* xsr; cudaGetSymbolAddress((void**)&xsr, g_xs_raw);
    __half* wh;  cudaGetSymbolAddress((void**)&wh, g_wh);
    float*  part; cudaGetSymbolAddress((void**)&part, g_part);
    __half* xn = xnr + XPAD;
    __half* xs = xsr + XPAD;

    cudaFuncSetAttribute(deform_kernel,
                         cudaFuncAttributeMaxDynamicSharedMemorySize, SM_TOTAL);

    prolog_kernel<<<4032, 256>>>(ref, dist, ow, ob, dw, out_diff,
                                 xn, xs, mw, me, wh);
    deform_kernel<<<1152, 256, SM_TOTAL>>>(xn, xs, mw, me, wh, part);
    reduce_kernel<<<(NOUT / 4 + 255) / 256, 256>>>((const float4*)part, db,
                                                   (float4*)out_feat);
}

// round 12
// speedup vs baseline: 1.0139x; 1.0139x over previous
#include <cuda_runtime.h>
#include <cuda_fp16.h>
#include <math.h>
#include <stdint.h>

// Problem constants
#define Bb   4
#define Cc   64
#define Hh   96
#define Ww   96
#define HW   (Hh*Ww)            // 9216
#define Oo   64
#define CIN3 (3*Cc)             // 192
#define IMG  (Cc*HW)            // 589824
#define NPIX (Bb*HW)            // 36864
#define NCH  27                 // K chunks of 64: K = k*192 + c (k-major)
#define NTOT (Bb*CIN3*HW)       // 7077888
#define XPAD 256
#define NOUT (Bb*Oo*HW)         // 2359296

// Scratch
__device__ float4 g_mw[Bb * 9 * HW];
__device__ int    g_me[Bb * 9 * HW];
__device__ __half g_xn_raw[NTOT + 2 * XPAD];
__device__ __half g_xs_raw[NTOT + 2 * XPAD];
__device__ __half g_wh[NCH * 64 * 64];
__device__ float  g_part[2 * NOUT];            // split-K partials

// ---------------- helpers ----------------
__device__ __forceinline__ uint32_t smem_to_u32(const void* p) {
    uint32_t a;
    asm("{ .reg .u64 t; cvta.to.shared.u64 t, %1; cvt.u32.u64 %0, t; }"
        : "=r"(a) : "l"(p));
    return a;
}
__device__ __forceinline__ void ldsm_x4(uint32_t* r, uint32_t addr) {
    asm volatile("ldmatrix.sync.aligned.m8n8.x4.shared.b16 {%0,%1,%2,%3}, [%4];"
        : "=r"(r[0]), "=r"(r[1]), "=r"(r[2]), "=r"(r[3]) : "r"(addr));
}
__device__ __forceinline__ void mma_f16(float* d, const uint32_t* a,
                                        uint32_t b0, uint32_t b1) {
    asm volatile("mma.sync.aligned.m16n8k16.row.col.f32.f16.f16.f32 "
        "{%0,%1,%2,%3}, {%4,%5,%6,%7}, {%8,%9}, {%0,%1,%2,%3};"
        : "+f"(d[0]), "+f"(d[1]), "+f"(d[2]), "+f"(d[3])
        : "r"(a[0]), "r"(a[1]), "r"(a[2]), "r"(a[3]), "r"(b0), "r"(b1));
}
__device__ __forceinline__ void cp_async16(uint32_t smem_addr, const void* gptr) {
    asm volatile("cp.async.cg.shared.global [%0], [%1], 16;"
        :: "r"(smem_addr), "l"(gptr));
}
#define CP_COMMIT() asm volatile("cp.async.commit_group;" ::: "memory")
#define CP_WAIT0()  asm volatile("cp.async.wait_group 0;" ::: "memory")

// ---------------------------------------------------------------------------
// Kernel 1: diff + fp16 NCHW repack (normal + shifted copies)
// ---------------------------------------------------------------------------
__global__ void repack_kernel(const float* __restrict__ ref,
                              const float* __restrict__ dist,
                              float* __restrict__ out_diff,
                              __half* __restrict__ xn,
                              __half* __restrict__ xs) {
    int i = blockIdx.x * blockDim.x + threadIdx.x;
    if (i >= NTOT) return;
    int b = i / (CIN3 * HW);
    int r = i - b * (CIN3 * HW);
    int c = r / HW;
    int e = r - c * HW;
    float v;
    if (c < Cc) {
        v = __ldg(ref + (b * Cc + c) * HW + e);
    } else if (c < 2 * Cc) {
        v = __ldg(dist + (b * Cc + (c - Cc)) * HW + e);
    } else {
        int cc = c - 2 * Cc;
        float rr = __ldg(ref  + (b * Cc + cc) * HW + e);
        float dd = __ldg(dist + (b * Cc + cc) * HW + e);
        v = (rr - dd) * (rr - dd);
        out_diff[(b * Cc + cc) * HW + e] = v;
    }
    __half h = __float2half_rn(v);
    xn[i] = h;
    if (i > 0) xs[i - 1] = h;
}

// ---------------------------------------------------------------------------
// Kernel 2: offset conv3x3 (Cin=64 -> 18) + fused bilinear meta (pair-based)
// ---------------------------------------------------------------------------
__global__ __launch_bounds__(128) void offset_meta_kernel(
        const float* __restrict__ ref,
        const float* __restrict__ ow, const float* __restrict__ ob,
        float4* __restrict__ mw, int* __restrict__ me) {
    __shared__ __align__(16) float s_w[576 * 20];
    int tid = threadIdx.x;
    for (int i = tid; i < 18 * 576; i += 128) {
        int o = i / 576, ck = i % 576;
        s_w[ck * 20 + o] = ow[i];
    }
    __syncthreads();

    int p = blockIdx.x * 128 + tid;
    int b = p / HW;
    int pix = p % HW;
    int y = pix / Ww, x = pix % Ww;

    int  idx9[9]; bool ok9[9];
#pragma unroll
    for (int ky = 0; ky < 3; ky++)
#pragma unroll
        for (int kx = 0; kx < 3; kx++) {
            int yy = y + ky - 1, xx = x + kx - 1;
            bool ok = (yy >= 0) && (yy < Hh) && (xx >= 0) && (xx < Ww);
            ok9[ky * 3 + kx] = ok;
            idx9[ky * 3 + kx] = (ok ? yy : 0) * Ww + (ok ? xx : 0);
        }

    float acc[18];
#pragma unroll
    for (int o = 0; o < 18; o++) acc[o] = 0.f;

    const float* xb = ref + b * IMG;
    for (int c = 0; c < Cc; c++) {
        const float* xc = xb + c * HW;
#pragma unroll
        for (int k = 0; k < 9; k++) {
            float v = ok9[k] ? __ldg(xc + idx9[k]) : 0.f;
            int base = (c * 9 + k) * 20;
            float4 w0 = *(const float4*)&s_w[base];
            float4 w1 = *(const float4*)&s_w[base + 4];
            float4 w2 = *(const float4*)&s_w[base + 8];
            float4 w3 = *(const float4*)&s_w[base + 12];
            float  wa = s_w[base + 16];
            float  wb = s_w[base + 17];
            acc[0]  += v * w0.x;  acc[1]  += v * w0.y;  acc[2]  += v * w0.z;  acc[3]  += v * w0.w;
            acc[4]  += v * w1.x;  acc[5]  += v * w1.y;  acc[6]  += v * w1.z;  acc[7]  += v * w1.w;
            acc[8]  += v * w2.x;  acc[9]  += v * w2.y;  acc[10] += v * w2.z;  acc[11] += v * w2.w;
            acc[12] += v * w3.x;  acc[13] += v * w3.y;  acc[14] += v * w3.z;  acc[15] += v * w3.w;
            acc[16] += v * wa;    acc[17] += v * wb;
        }
    }

#pragma unroll
    for (int k = 0; k < 9; k++) {
        float offy = acc[2 * k]     + __ldg(ob + 2 * k);
        float offx = acc[2 * k + 1] + __ldg(ob + 2 * k + 1);
        float py = (float)(y - 1 + k / 3) + offy;
        float px = (float)(x - 1 + k % 3) + offx;
        float fy = floorf(py), fx = floorf(px);
        int y0 = (int)fy, x0 = (int)fx;
        float dy = py - fy, dx = px - fx;
        float wv[4];
#pragma unroll
        for (int t = 0; t < 4; t++) {
            int yt = y0 + (t >> 1);
            int xt = x0 + (t & 1);
            float wt = ((t >> 1) ? dy : (1.f - dy)) * ((t & 1) ? dx : (1.f - dx));
            bool valid = (yt >= 0) && (yt < Hh) && (xt >= 0) && (xt < Ww);
            wv[t] = valid ? wt : 0.f;
        }
        int y0c = y0 < -1 ? -1 : (y0 > Hh ? Hh : y0);
        int x0c = x0 < -1 ? -1 : (x0 > Ww ? Ww : x0);
        int e0 = y0c * Ww + x0c;
        int mo = (b * 9 + k) * HW + pix;
        mw[mo] = make_float4(wv[0], wv[1], wv[2], wv[3]);
        me[mo] = e0;
    }
}

// ---------------------------------------------------------------------------
// Kernel 3: weight prep -> fp16 B tiles, XOR-swizzled [n][k] layout
// ---------------------------------------------------------------------------
__global__ void wprep_kernel(const float* __restrict__ dw,
                             __half* __restrict__ wh) {
    int i = blockIdx.x * blockDim.x + threadIdx.x;
    if (i >= NCH * 64 * 64) return;
    int c  = i & 63;
    int o  = (i >> 6) & 63;
    int ch = i >> 12;
    int k  = ch / 3;
    int cg = (ch % 3) * 64 + c;
    float v = __ldg(dw + o * (CIN3 * 9) + cg * 9 + k);
    int elem = o * 64 + (((c >> 3) ^ (o & 7)) << 3) + (c & 7);
    wh[ch * 4096 + elem] = __float2half_rn(v);
}

// ---------------------------------------------------------------------------
// Deform (split-K x2): block = M64 x N64, 256 thr (8 warps, warp tile 16x32),
// s = bid&1 selects chunks [0,14) or [14,27). Partials (fp32) to g_part.
// Per buffer (16KB): A@0 8K | B@8K 8K. 4 blocks/SM.
// ---------------------------------------------------------------------------
#define SM_BUF   16384
#define SM_AHOF  0
#define SM_BHOF  8192
#define SM_TOTAL (2 * SM_BUF)

__global__ __launch_bounds__(256, 4) void deform_kernel(
        const __half* __restrict__ xn, const __half* __restrict__ xs,
        const float4* __restrict__ mw, const int* __restrict__ me,
        const __half* __restrict__ wh,
        float* __restrict__ part) {
    extern __shared__ char smem[];
    uint32_t sb = smem_to_u32(smem);

    int tid  = threadIdx.x;
    int lane = tid & 31;
    int warp = tid >> 5;
    int bid  = blockIdx.x;
    int s    = bid & 1;
    int tile = bid >> 1;
    int b    = tile / 144;
    int pix0 = (tile % 144) * 64;

    int ch0 = s ? 14 : 0;
    int ch1 = s ? 27 : 14;

    int p  = tid & 63;          // pixel
    int cq = tid >> 6;          // channel quarter (16 ch)
    uint32_t a_sts = (uint32_t)p * 128;

    int m0 = (warp & 3) * 16;
    int n0 = (warp >> 2) * 32;

    float acc[4][4];
#pragma unroll
    for (int j = 0; j < 4; j++)
#pragma unroll
        for (int q = 0; q < 4; q++) acc[j][q] = 0.f;

    uint32_t a_m  = lane & 15;
    uint32_t a_kc = lane >> 4;
    uint32_t b_n  = ((lane >> 4) << 3) + (lane & 7);
    uint32_t b_kc = (lane >> 3) & 1;

    auto build_g = [&](int ch, int g2, __half2 wtop, __half2 wbot,
                       const __half2* srcp) {
        char* bufc = smem + (ch & 1) * SM_BUF;
        __half v[8];
#pragma unroll
        for (int j = 0; j < 8; j++) {
            const __half2* pl = srcp + (g2 * 8 + j) * (HW / 2);
            __half2 a  = __ldg(pl);
            __half2 bb = __ldg(pl + (Ww / 2));
            __half2 t  = __hfma2(wbot, bb, __hmul2(wtop, a));
            v[j] = __hadd(__low2half(t), __high2half(t));
        }
        uint32_t hp[4];
#pragma unroll
        for (int jj = 0; jj < 4; jj++) {
            __half2 hb = __halves2half2(v[2 * jj], v[2 * jj + 1]);
            hp[jj] = *(uint32_t*)&hb;
        }
        int kc = cq * 2 + g2;
        uint32_t off = a_sts + (uint32_t)((kc ^ (p & 7)) << 4);
        *(uint4*)(bufc + SM_AHOF + off) = make_uint4(hp[0], hp[1], hp[2], hp[3]);
    };

    auto chunk_meta = [&](int ch, __half2& wtop, __half2& wbot,
                          const __half2*& srcp) {
        int k   = ch / 3;
        int cbl = ch - 3 * k;
        float4 w = __ldg(mw + (b * 9 + k) * HW + pix0 + p);
        int   e0 = __ldg(me + (b * 9 + k) * HW + pix0 + p);
        wtop = __floats2half2_rn(w.x, w.y);
        wbot = __floats2half2_rn(w.z, w.w);
        int sel = e0 & 1;
        int h2base = (e0 - sel) >> 1;
        const __half* base = sel ? xs : xn;
        srcp = (const __half2*)base
             + (size_t)(b * CIN3 + cbl * 64 + cq * 16) * (HW / 2)
             + h2base;
    };

    auto stage_B = [&](int ch) {
        uint32_t bufb = sb + (ch & 1) * SM_BUF;
        const char* gh = (const char*)(wh + ch * 4096);
        cp_async16(bufb + SM_BHOF + tid * 16, gh + tid * 16);
        cp_async16(bufb + SM_BHOF + (tid + 256) * 16, gh + (tid + 256) * 16);
        CP_COMMIT();
    };

    // prologue: first chunk
    stage_B(ch0);
    {
        __half2 wtop, wbot; const __half2* srcp;
        chunk_meta(ch0, wtop, wbot, srcp);
        build_g(ch0, 0, wtop, wbot, srcp);
        build_g(ch0, 1, wtop, wbot, srcp);
    }
    CP_WAIT0();
    __syncthreads();

    for (int ch = ch0; ch < ch1; ch++) {
        int nxt = ch + 1;
        bool has_nxt = (nxt < ch1);
        if (has_nxt) stage_B(nxt);

        __half2 nwt = __float2half2_rn(0.f), nwb = __float2half2_rn(0.f);
        const __half2* nsrc = (const __half2*)xn;
        if (has_nxt) chunk_meta(nxt, nwt, nwb, nsrc);

        uint32_t bufb = sb + (ch & 1) * SM_BUF;
#pragma unroll
        for (int ks = 0; ks < 4; ks++) {
            uint32_t ah[4], bh[2][4];
            {
                uint32_t row = m0 + a_m;
                uint32_t aoff = row * 128 + ((((ks << 1) + a_kc) ^ (row & 7)) << 4);
                ldsm_x4(ah, bufb + SM_AHOF + aoff);
            }
#pragma unroll
            for (int g = 0; g < 2; g++) {
                uint32_t n  = n0 + g * 16 + b_n;
                uint32_t kc = (ks << 1) + b_kc;
                uint32_t boff = n * 128 + ((kc ^ (n & 7)) << 4);
                ldsm_x4(bh[g], bufb + SM_BHOF + boff);
            }
#pragma unroll
            for (int g = 0; g < 2; g++)
#pragma unroll
                for (int s2 = 0; s2 < 2; s2++) {
                    int ni = g * 2 + s2;
                    mma_f16(acc[ni], ah, bh[g][2 * s2], bh[g][2 * s2 + 1]);
                }
            if (has_nxt && (ks == 0 || ks == 2))
                build_g(nxt, ks >> 1, nwt, nwb, nsrc);
        }

        CP_WAIT0();
        __syncthreads();
    }

    // epilogue: store fp32 partials
    float* pp = part + (size_t)s * NOUT;
    int r  = lane >> 2;
    int cp = (lane & 3) * 2;
    int pixb = pix0 + m0 + r;
#pragma unroll
    for (int ni = 0; ni < 4; ni++) {
        int o = n0 + ni * 8 + cp;
        float* o0 = pp + (size_t)(b * Oo + o) * HW;
        float* o1 = pp + (size_t)(b * Oo + o + 1) * HW;
        o0[pixb]     = acc[ni][0];
        o1[pixb]     = acc[ni][1];
        o0[pixb + 8] = acc[ni][2];
        o1[pixb + 8] = acc[ni][3];
    }
}

// ---------------------------------------------------------------------------
// Reduce: out = relu(p0 + p1 + bias)
// ---------------------------------------------------------------------------
__global__ __launch_bounds__(256) void reduce_kernel(
        const float4* __restrict__ part, const float* __restrict__ db,
        float4* __restrict__ out) {
    int i4 = blockIdx.x * 256 + threadIdx.x;
    if (i4 >= NOUT / 4) return;
    float4 p0 = __ldg(part + i4);
    float4 p1 = __ldg(part + NOUT / 4 + i4);
    int o = (i4 / (HW / 4)) % Oo;
    float bias = __ldg(db + o);
    float4 v;
    v.x = fmaxf(p0.x + p1.x + bias, 0.f);
    v.y = fmaxf(p0.y + p1.y + bias, 0.f);
    v.z = fmaxf(p0.z + p1.z + bias, 0.f);
    v.w = fmaxf(p0.w + p1.w + bias, 0.f);
    out[i4] = v;
}

// ---------------------------------------------------------------------------
extern "C" void kernel_launch(void* const* d_in, const int* in_sizes, int n_in,
                              void* d_out, int out_size) {
    const float* ref  = (const float*)d_in[0];
    const float* dist = (const float*)d_in[1];
    const float* ow   = (const float*)d_in[2];
    const float* ob   = (const float*)d_in[3];
    const float* dw   = (const float*)d_in[4];
    const float* db   = (const float*)d_in[5];
    float* out = (float*)d_out;
    float* out_feat = out;
    float* out_diff = out + Bb * IMG;

    float4* mw;  cudaGetSymbolAddress((void**)&mw, g_mw);
    int*    me;  cudaGetSymbolAddress((void**)&me, g_me);
    __half* xnr; cudaGetSymbolAddress((void**)&xnr, g_xn_raw);
    __half* xsr; cudaGetSymbolAddress((void**)&xsr, g_xs_raw);
    __half* wh;  cudaGetSymbolAddress((void**)&wh, g_wh);
    float*  part; cudaGetSymbolAddress((void**)&part, g_part);
    __half* xn = xnr + XPAD;
    __half* xs = xsr + XPAD;

    cudaFuncSetAttribute(deform_kernel,
                         cudaFuncAttributeMaxDynamicSharedMemorySize, SM_TOTAL);

    repack_kernel<<<(NTOT + 255) / 256, 256>>>(ref, dist, out_diff, xn, xs);
    offset_meta_kernel<<<NPIX / 128, 128>>>(ref, ow, ob, mw, me);
    wprep_kernel<<<(NCH * 64 * 64 + 255) / 256, 256>>>(dw, wh);
    deform_kernel<<<1152, 256, SM_TOTAL>>>(xn, xs, mw, me, wh, part);
    reduce_kernel<<<(NOUT / 4 + 255) / 256, 256>>>((const float4*)part, db,
                                                   (float4*)out_feat);
}

// round 13
// speedup vs baseline: 1.0850x; 1.0702x over previous
#include <cuda_runtime.h>
#include <cuda_fp16.h>
#include <math.h>
#include <stdint.h>

// Problem constants
#define Bb   4
#define Cc   64
#define Hh   96
#define Ww   96
#define HW   (Hh*Ww)            // 9216
#define Oo   64
#define CIN3 (3*Cc)             // 192
#define IMG  (Cc*HW)            // 589824
#define NPIX (Bb*HW)            // 36864
#define NCH  27                 // K chunks of 64: K = k*192 + c (k-major)
#define NTOT (Bb*CIN3*HW)       // 7077888
#define XPAD 256

// Scratch
__device__ float4 g_mw[Bb * 9 * HW];
__device__ int    g_me[Bb * 9 * HW];
__device__ __half g_xn_raw[NTOT + 2 * XPAD];
__device__ __half g_xs_raw[NTOT + 2 * XPAD];
__device__ __half g_wh[NCH * 64 * 64];

// ---------------- helpers ----------------
__device__ __forceinline__ uint32_t smem_to_u32(const void* p) {
    uint32_t a;
    asm("{ .reg .u64 t; cvta.to.shared.u64 t, %1; cvt.u32.u64 %0, t; }"
        : "=r"(a) : "l"(p));
    return a;
}
__device__ __forceinline__ void ldsm_x4(uint32_t* r, uint32_t addr) {
    asm volatile("ldmatrix.sync.aligned.m8n8.x4.shared.b16 {%0,%1,%2,%3}, [%4];"
        : "=r"(r[0]), "=r"(r[1]), "=r"(r[2]), "=r"(r[3]) : "r"(addr));
}
__device__ __forceinline__ void mma_f16(float* d, const uint32_t* a,
                                        uint32_t b0, uint32_t b1) {
    asm volatile("mma.sync.aligned.m16n8k16.row.col.f32.f16.f16.f32 "
        "{%0,%1,%2,%3}, {%4,%5,%6,%7}, {%8,%9}, {%0,%1,%2,%3};"
        : "+f"(d[0]), "+f"(d[1]), "+f"(d[2]), "+f"(d[3])
        : "r"(a[0]), "r"(a[1]), "r"(a[2]), "r"(a[3]), "r"(b0), "r"(b1));
}
__device__ __forceinline__ void cp_async16(uint32_t smem_addr, const void* gptr) {
    asm volatile("cp.async.cg.shared.global [%0], [%1], 16;"
        :: "r"(smem_addr), "l"(gptr));
}
#define CP_COMMIT() asm volatile("cp.async.commit_group;" ::: "memory")
#define CP_WAIT0()  asm volatile("cp.async.wait_group 0;" ::: "memory")

// ---------------------------------------------------------------------------
// Kernel 1: diff + fp16 NCHW repack (normal + shifted copies)
// ---------------------------------------------------------------------------
__global__ void repack_kernel(const float* __restrict__ ref,
                              const float* __restrict__ dist,
                              float* __restrict__ out_diff,
                              __half* __restrict__ xn,
                              __half* __restrict__ xs) {
    int i = blockIdx.x * blockDim.x + threadIdx.x;
    if (i >= NTOT) return;
    int b = i / (CIN3 * HW);
    int r = i - b * (CIN3 * HW);
    int c = r / HW;
    int e = r - c * HW;
    float v;
    if (c < Cc) {
        v = __ldg(ref + (b * Cc + c) * HW + e);
    } else if (c < 2 * Cc) {
        v = __ldg(dist + (b * Cc + (c - Cc)) * HW + e);
    } else {
        int cc = c - 2 * Cc;
        float rr = __ldg(ref  + (b * Cc + cc) * HW + e);
        float dd = __ldg(dist + (b * Cc + cc) * HW + e);
        v = (rr - dd) * (rr - dd);
        out_diff[(b * Cc + cc) * HW + e] = v;
    }
    __half h = __float2half_rn(v);
    xn[i] = h;
    if (i > 0) xs[i - 1] = h;
}

// ---------------------------------------------------------------------------
// Kernel 2: offset conv3x3 (Cin=64 -> 18) + fused bilinear meta (pair-based)
// ---------------------------------------------------------------------------
__global__ __launch_bounds__(128) void offset_meta_kernel(
        const float* __restrict__ ref,
        const float* __restrict__ ow, const float* __restrict__ ob,
        float4* __restrict__ mw, int* __restrict__ me) {
    __shared__ __align__(16) float s_w[576 * 20];
    int tid = threadIdx.x;
    for (int i = tid; i < 18 * 576; i += 128) {
        int o = i / 576, ck = i % 576;
        s_w[ck * 20 + o] = ow[i];
    }
    __syncthreads();

    int p = blockIdx.x * 128 + tid;
    int b = p / HW;
    int pix = p % HW;
    int y = pix / Ww, x = pix % Ww;

    int  idx9[9]; bool ok9[9];
#pragma unroll
    for (int ky = 0; ky < 3; ky++)
#pragma unroll
        for (int kx = 0; kx < 3; kx++) {
            int yy = y + ky - 1, xx = x + kx - 1;
            bool ok = (yy >= 0) && (yy < Hh) && (xx >= 0) && (xx < Ww);
            ok9[ky * 3 + kx] = ok;
            idx9[ky * 3 + kx] = (ok ? yy : 0) * Ww + (ok ? xx : 0);
        }

    float acc[18];
#pragma unroll
    for (int o = 0; o < 18; o++) acc[o] = 0.f;

    const float* xb = ref + b * IMG;
    for (int c = 0; c < Cc; c++) {
        const float* xc = xb + c * HW;
#pragma unroll
        for (int k = 0; k < 9; k++) {
            float v = ok9[k] ? __ldg(xc + idx9[k]) : 0.f;
            int base = (c * 9 + k) * 20;
            float4 w0 = *(const float4*)&s_w[base];
            float4 w1 = *(const float4*)&s_w[base + 4];
            float4 w2 = *(const float4*)&s_w[base + 8];
            float4 w3 = *(const float4*)&s_w[base + 12];
            float  wa = s_w[base + 16];
            float  wb = s_w[base + 17];
            acc[0]  += v * w0.x;  acc[1]  += v * w0.y;  acc[2]  += v * w0.z;  acc[3]  += v * w0.w;
            acc[4]  += v * w1.x;  acc[5]  += v * w1.y;  acc[6]  += v * w1.z;  acc[7]  += v * w1.w;
            acc[8]  += v * w2.x;  acc[9]  += v * w2.y;  acc[10] += v * w2.z;  acc[11] += v * w2.w;
            acc[12] += v * w3.x;  acc[13] += v * w3.y;  acc[14] += v * w3.z;  acc[15] += v * w3.w;
            acc[16] += v * wa;    acc[17] += v * wb;
        }
    }

#pragma unroll
    for (int k = 0; k < 9; k++) {
        float offy = acc[2 * k]     + __ldg(ob + 2 * k);
        float offx = acc[2 * k + 1] + __ldg(ob + 2 * k + 1);
        float py = (float)(y - 1 + k / 3) + offy;
        float px = (float)(x - 1 + k % 3) + offx;
        float fy = floorf(py), fx = floorf(px);
        int y0 = (int)fy, x0 = (int)fx;
        float dy = py - fy, dx = px - fx;
        float wv[4];
#pragma unroll
        for (int t = 0; t < 4; t++) {
            int yt = y0 + (t >> 1);
            int xt = x0 + (t & 1);
            float wt = ((t >> 1) ? dy : (1.f - dy)) * ((t & 1) ? dx : (1.f - dx));
            bool valid = (yt >= 0) && (yt < Hh) && (xt >= 0) && (xt < Ww);
            wv[t] = valid ? wt : 0.f;
        }
        int y0c = y0 < -1 ? -1 : (y0 > Hh ? Hh : y0);
        int x0c = x0 < -1 ? -1 : (x0 > Ww ? Ww : x0);
        int e0 = y0c * Ww + x0c;
        int mo = (b * 9 + k) * HW + pix;
        mw[mo] = make_float4(wv[0], wv[1], wv[2], wv[3]);
        me[mo] = e0;
    }
}

// ---------------------------------------------------------------------------
// Kernel 3: weight prep -> fp16 B tiles, XOR-swizzled [n][k] layout
// ---------------------------------------------------------------------------
__global__ void wprep_kernel(const float* __restrict__ dw,
                             __half* __restrict__ wh) {
    int i = blockIdx.x * blockDim.x + threadIdx.x;
    if (i >= NCH * 64 * 64) return;
    int c  = i & 63;
    int o  = (i >> 6) & 63;
    int ch = i >> 12;
    int k  = ch / 3;
    int cg = (ch % 3) * 64 + c;
    float v = __ldg(dw + o * (CIN3 * 9) + cg * 9 + k);
    int elem = o * 64 + (((c >> 3) ^ (o & 7)) << 3) + (c & 7);
    wh[ch * 4096 + elem] = __float2half_rn(v);
}

// ---------------------------------------------------------------------------
// Kernel 4: deformable conv, M128 x N64 tile, 512 threads (16 warps,
// warp tile 16x32), mma.sync fp16, double-buffered, paired-tap fp16 gather.
// Per buffer (24KB): A@0 16K | B@16K 8K. 2 blocks/SM -> 32 warps/SM.
// ---------------------------------------------------------------------------
#define SM_BUF   24576
#define SM_AHOF  0
#define SM_BHOF  16384
#define SM_TOTAL (2 * SM_BUF)

__global__ __launch_bounds__(512, 2) void deform_kernel(
        const __half* __restrict__ xn, const __half* __restrict__ xs,
        const float4* __restrict__ mw, const int* __restrict__ me,
        const __half* __restrict__ wh,
        const float* __restrict__ db, float* __restrict__ out) {
    extern __shared__ char smem[];
    uint32_t sb = smem_to_u32(smem);

    int tid  = threadIdx.x;
    int lane = tid & 31;
    int warp = tid >> 5;
    int b    = blockIdx.x / 72;
    int pix0 = (blockIdx.x % 72) * 128;

    int p  = tid & 127;          // pixel within tile
    int cq = tid >> 7;           // channel quarter (16 ch), 0-3
    uint32_t a_sts = (uint32_t)p * 128;

    int m0 = (warp & 7) * 16;
    int n0 = (warp >> 3) * 32;

    float acc[4][4];
#pragma unroll
    for (int j = 0; j < 4; j++)
#pragma unroll
        for (int q = 0; q < 4; q++) acc[j][q] = 0.f;

    uint32_t a_m  = lane & 15;
    uint32_t a_kc = lane >> 4;
    uint32_t b_n  = ((lane >> 4) << 3) + (lane & 7);
    uint32_t b_kc = (lane >> 3) & 1;

    // build one 8-channel group g2 (0/1) of chunk ch (this thread's quarter)
    auto build_g = [&](int ch, int g2, __half2 wtop, __half2 wbot,
                       const __half2* srcp) {
        char* bufc = smem + (ch & 1) * SM_BUF;
        __half v[8];
#pragma unroll
        for (int j = 0; j < 8; j++) {
            const __half2* pl = srcp + (g2 * 8 + j) * (HW / 2);
            __half2 a  = __ldg(pl);
            __half2 bb = __ldg(pl + (Ww / 2));
            __half2 t  = __hfma2(wbot, bb, __hmul2(wtop, a));
            v[j] = __hadd(__low2half(t), __high2half(t));
        }
        uint32_t hp[4];
#pragma unroll
        for (int jj = 0; jj < 4; jj++) {
            __half2 hb = __halves2half2(v[2 * jj], v[2 * jj + 1]);
            hp[jj] = *(uint32_t*)&hb;
        }
        int kc = cq * 2 + g2;
        uint32_t off = a_sts + (uint32_t)((kc ^ (p & 7)) << 4);
        *(uint4*)(bufc + SM_AHOF + off) = make_uint4(hp[0], hp[1], hp[2], hp[3]);
    };

    auto chunk_meta = [&](int ch, __half2& wtop, __half2& wbot,
                          const __half2*& srcp) {
        int k   = ch / 3;
        int cbl = ch - 3 * k;
        float4 w = __ldg(mw + (b * 9 + k) * HW + pix0 + p);
        int   e0 = __ldg(me + (b * 9 + k) * HW + pix0 + p);
        wtop = __floats2half2_rn(w.x, w.y);
        wbot = __floats2half2_rn(w.z, w.w);
        int sel = e0 & 1;
        int h2base = (e0 - sel) >> 1;
        const __half* base = sel ? xs : xn;
        srcp = (const __half2*)base
             + (size_t)(b * CIN3 + cbl * 64 + cq * 16) * (HW / 2)
             + h2base;
    };

    auto stage_B = [&](int ch) {
        if (tid < 512) {
            uint32_t bufb = sb + (ch & 1) * SM_BUF;
            const char* gh = (const char*)(wh + ch * 4096);
            cp_async16(bufb + SM_BHOF + tid * 16, gh + tid * 16);
        }
        CP_COMMIT();
    };

    // prologue: chunk 0
    stage_B(0);
    {
        __half2 wtop, wbot; const __half2* srcp;
        chunk_meta(0, wtop, wbot, srcp);
        build_g(0, 0, wtop, wbot, srcp);
        build_g(0, 1, wtop, wbot, srcp);
    }
    CP_WAIT0();
    __syncthreads();

    for (int ch = 0; ch < NCH; ch++) {
        int nxt = ch + 1;
        bool has_nxt = (nxt < NCH);
        if (has_nxt) stage_B(nxt);

        __half2 nwt = __float2half2_rn(0.f), nwb = __float2half2_rn(0.f);
        const __half2* nsrc = (const __half2*)xn;
        if (has_nxt) chunk_meta(nxt, nwt, nwb, nsrc);

        uint32_t bufb = sb + (ch & 1) * SM_BUF;
#pragma unroll
        for (int ks = 0; ks < 4; ks++) {
            uint32_t ah[4], bh[2][4];
            {
                uint32_t row = m0 + a_m;
                uint32_t aoff = row * 128 + ((((ks << 1) + a_kc) ^ (row & 7)) << 4);
                ldsm_x4(ah, bufb + SM_AHOF + aoff);
            }
#pragma unroll
            for (int g = 0; g < 2; g++) {
                uint32_t n  = n0 + g * 16 + b_n;
                uint32_t kc = (ks << 1) + b_kc;
                uint32_t boff = n * 128 + ((kc ^ (n & 7)) << 4);
                ldsm_x4(bh[g], bufb + SM_BHOF + boff);
            }
#pragma unroll
            for (int g = 0; g < 2; g++)
#pragma unroll
                for (int s2 = 0; s2 < 2; s2++) {
                    int ni = g * 2 + s2;
                    mma_f16(acc[ni], ah, bh[g][2 * s2], bh[g][2 * s2 + 1]);
                }
            if (has_nxt && (ks == 0 || ks == 2))
                build_g(nxt, ks >> 1, nwt, nwb, nsrc);
        }

        CP_WAIT0();
        __syncthreads();
    }

    // epilogue: bias + relu
    int r  = lane >> 2;
    int cp = (lane & 3) * 2;
    int pixb = pix0 + m0 + r;
#pragma unroll
    for (int ni = 0; ni < 4; ni++) {
        int o = n0 + ni * 8 + cp;
        float b0v = __ldg(db + o);
        float b1v = __ldg(db + o + 1);
        float* o0 = out + (size_t)(b * Oo + o) * HW;
        float* o1 = out + (size_t)(b * Oo + o + 1) * HW;
        float v;
        v = acc[ni][0] + b0v; o0[pixb]     = v > 0.f ? v : 0.f;
        v = acc[ni][1] + b1v; o1[pixb]     = v > 0.f ? v : 0.f;
        v = acc[ni][2] + b0v; o0[pixb + 8] = v > 0.f ? v : 0.f;
        v = acc[ni][3] + b1v; o1[pixb + 8] = v > 0.f ? v : 0.f;
    }
}

// ---------------------------------------------------------------------------
extern "C" void kernel_launch(void* const* d_in, const int* in_sizes, int n_in,
                              void* d_out, int out_size) {
    const float* ref  = (const float*)d_in[0];
    const float* dist = (const float*)d_in[1];
    const float* ow   = (const float*)d_in[2];
    const float* ob   = (const float*)d_in[3];
    const float* dw   = (const float*)d_in[4];
    const float* db   = (const float*)d_in[5];
    float* out = (float*)d_out;
    float* out_feat = out;
    float* out_diff = out + Bb * IMG;

    float4* mw;  cudaGetSymbolAddress((void**)&mw, g_mw);
    int*    me;  cudaGetSymbolAddress((void**)&me, g_me);
    __half* xnr; cudaGetSymbolAddress((void**)&xnr, g_xn_raw);
    __half* xsr; cudaGetSymbolAddress((void**)&xsr, g_xs_raw);
    __half* wh;  cudaGetSymbolAddress((void**)&wh, g_wh);
    __half* xn = xnr + XPAD;
    __half* xs = xsr + XPAD;

    cudaFuncSetAttribute(deform_kernel,
                         cudaFuncAttributeMaxDynamicSharedMemorySize, SM_TOTAL);

    repack_kernel<<<(NTOT + 255) / 256, 256>>>(ref, dist, out_diff, xn, xs);
    offset_meta_kernel<<<NPIX / 128, 128>>>(ref, ow, ob, mw, me);
    wprep_kernel<<<(NCH * 64 * 64 + 255) / 256, 256>>>(dw, wh);
    deform_kernel<<<NPIX / 128, 512, SM_TOTAL>>>(xn, xs, mw, me, wh, db, out_feat);
}

// round 14
// speedup vs baseline: 1.1610x; 1.0700x over previous
#include <cuda_runtime.h>
#include <cuda_fp16.h>
#include <math.h>
#include <stdint.h>

// Problem constants
#define Bb   4
#define Cc   64
#define Hh   96
#define Ww   96
#define HW   (Hh*Ww)            // 9216
#define Oo   64
#define CIN3 (3*Cc)             // 192
#define IMG  (Cc*HW)            // 589824
#define NPIX (Bb*HW)            // 36864
#define NCH  27                 // K chunks of 64: K = k*192 + c (k-major)
#define NTOT (Bb*CIN3*HW)       // 7077888
#define XPAD 256

// Scratch
__device__ float4 g_mw[Bb * 9 * HW];
__device__ int    g_me[Bb * 9 * HW];
__device__ __half g_xn_raw[NTOT + 2 * XPAD];
__device__ __half g_xs_raw[NTOT + 2 * XPAD];
__device__ __half g_wh[NCH * 64 * 64];

// ---------------- helpers ----------------
__device__ __forceinline__ uint32_t smem_to_u32(const void* p) {
    uint32_t a;
    asm("{ .reg .u64 t; cvta.to.shared.u64 t, %1; cvt.u32.u64 %0, t; }"
        : "=r"(a) : "l"(p));
    return a;
}
__device__ __forceinline__ void ldsm_x4(uint32_t* r, uint32_t addr) {
    asm volatile("ldmatrix.sync.aligned.m8n8.x4.shared.b16 {%0,%1,%2,%3}, [%4];"
        : "=r"(r[0]), "=r"(r[1]), "=r"(r[2]), "=r"(r[3]) : "r"(addr));
}
__device__ __forceinline__ void mma_f16(float* d, const uint32_t* a,
                                        uint32_t b0, uint32_t b1) {
    asm volatile("mma.sync.aligned.m16n8k16.row.col.f32.f16.f16.f32 "
        "{%0,%1,%2,%3}, {%4,%5,%6,%7}, {%8,%9}, {%0,%1,%2,%3};"
        : "+f"(d[0]), "+f"(d[1]), "+f"(d[2]), "+f"(d[3])
        : "r"(a[0]), "r"(a[1]), "r"(a[2]), "r"(a[3]), "r"(b0), "r"(b1));
}
__device__ __forceinline__ void cp_async16(uint32_t smem_addr, const void* gptr) {
    asm volatile("cp.async.cg.shared.global [%0], [%1], 16;"
        :: "r"(smem_addr), "l"(gptr));
}
#define CP_COMMIT() asm volatile("cp.async.commit_group;" ::: "memory")
#define CP_WAIT0()  asm volatile("cp.async.wait_group 0;" ::: "memory")

// packed f32x2 FMA (IEEE fp32 per lane)
__device__ __forceinline__ void ffma2(unsigned long long& c,
                                      unsigned long long a,
                                      unsigned long long b) {
    asm("fma.rn.f32x2 %0, %1, %2, %0;" : "+l"(c) : "l"(a), "l"(b));
}
__device__ __forceinline__ unsigned long long dup2(float x) {
    unsigned long long d;
    asm("mov.b64 %0, {%1, %1};" : "=l"(d) : "r"(__float_as_uint(x)));
    return d;
}
__device__ __forceinline__ void unpk2(float& lo, float& hi, unsigned long long v) {
    unsigned int l, h;
    asm("mov.b64 {%0, %1}, %2;" : "=r"(l), "=r"(h) : "l"(v));
    lo = __uint_as_float(l); hi = __uint_as_float(h);
}

// ---------------------------------------------------------------------------
// Kernel 1: diff + fp16 NCHW repack (normal + shifted copies)
// ---------------------------------------------------------------------------
__global__ void repack_kernel(const float* __restrict__ ref,
                              const float* __restrict__ dist,
                              float* __restrict__ out_diff,
                              __half* __restrict__ xn,
                              __half* __restrict__ xs) {
    int i = blockIdx.x * blockDim.x + threadIdx.x;
    if (i >= NTOT) return;
    int b = i / (CIN3 * HW);
    int r = i - b * (CIN3 * HW);
    int c = r / HW;
    int e = r - c * HW;
    float v;
    if (c < Cc) {
        v = __ldg(ref + (b * Cc + c) * HW + e);
    } else if (c < 2 * Cc) {
        v = __ldg(dist + (b * Cc + (c - Cc)) * HW + e);
    } else {
        int cc = c - 2 * Cc;
        float rr = __ldg(ref  + (b * Cc + cc) * HW + e);
        float dd = __ldg(dist + (b * Cc + cc) * HW + e);
        v = (rr - dd) * (rr - dd);
        out_diff[(b * Cc + cc) * HW + e] = v;
    }
    __half h = __float2half_rn(v);
    xn[i] = h;
    if (i > 0) xs[i - 1] = h;
}

// ---------------------------------------------------------------------------
// Kernel 2: offset conv3x3 + bilinear meta. f32x2 packed FMA, 2 px/thread
// (p and p + NPIX/2 share all weight LDS). 144 blocks x 128 threads.
// ---------------------------------------------------------------------------
__global__ __launch_bounds__(128) void offset_meta_kernel(
        const float* __restrict__ ref,
        const float* __restrict__ ow, const float* __restrict__ ob,
        float4* __restrict__ mw, int* __restrict__ me) {
    __shared__ __align__(16) float s_w[576 * 20];
    int tid = threadIdx.x;
    for (int i = tid; i < 18 * 576; i += 128) {
        int o = i / 576, ck = i % 576;
        s_w[ck * 20 + o] = ow[i];
    }
    __syncthreads();

    int pp[2];
    pp[0] = blockIdx.x * 128 + tid;
    pp[1] = pp[0] + NPIX / 2;

    int  idx9[2][9];
    bool ok9[2][9];
    const float* xb[2];
    int yy_[2], xx_[2], b_[2], pix_[2];
#pragma unroll
    for (int hf = 0; hf < 2; hf++) {
        int p = pp[hf];
        int b = p / HW;
        int pix = p % HW;
        int y = pix / Ww, x = pix % Ww;
        b_[hf] = b; pix_[hf] = pix; yy_[hf] = y; xx_[hf] = x;
        xb[hf] = ref + b * IMG;
#pragma unroll
        for (int ky = 0; ky < 3; ky++)
#pragma unroll
            for (int kx = 0; kx < 3; kx++) {
                int yt = y + ky - 1, xt = x + kx - 1;
                bool ok = (yt >= 0) && (yt < Hh) && (xt >= 0) && (xt < Ww);
                ok9[hf][ky * 3 + kx] = ok;
                idx9[hf][ky * 3 + kx] = (ok ? yt : 0) * Ww + (ok ? xt : 0);
            }
    }

    unsigned long long acc[2][9];
#pragma unroll
    for (int hf = 0; hf < 2; hf++)
#pragma unroll
        for (int j = 0; j < 9; j++) acc[hf][j] = 0ull;

    for (int c = 0; c < Cc; c++) {
        const float* xc0 = xb[0] + c * HW;
        const float* xc1 = xb[1] + c * HW;
#pragma unroll
        for (int k = 0; k < 9; k++) {
            const unsigned long long* wp =
                (const unsigned long long*)&s_w[(c * 9 + k) * 20];
            unsigned long long w0 = wp[0], w1 = wp[1], w2 = wp[2];
            unsigned long long w3 = wp[3], w4 = wp[4], w5 = wp[5];
            unsigned long long w6 = wp[6], w7 = wp[7], w8 = wp[8];
            float vA = ok9[0][k] ? __ldg(xc0 + idx9[0][k]) : 0.f;
            float vB = ok9[1][k] ? __ldg(xc1 + idx9[1][k]) : 0.f;
            unsigned long long dA = dup2(vA), dB = dup2(vB);
            ffma2(acc[0][0], dA, w0); ffma2(acc[1][0], dB, w0);
            ffma2(acc[0][1], dA, w1); ffma2(acc[1][1], dB, w1);
            ffma2(acc[0][2], dA, w2); ffma2(acc[1][2], dB, w2);
            ffma2(acc[0][3], dA, w3); ffma2(acc[1][3], dB, w3);
            ffma2(acc[0][4], dA, w4); ffma2(acc[1][4], dB, w4);
            ffma2(acc[0][5], dA, w5); ffma2(acc[1][5], dB, w5);
            ffma2(acc[0][6], dA, w6); ffma2(acc[1][6], dB, w6);
            ffma2(acc[0][7], dA, w7); ffma2(acc[1][7], dB, w7);
            ffma2(acc[0][8], dA, w8); ffma2(acc[1][8], dB, w8);
        }
    }

#pragma unroll
    for (int hf = 0; hf < 2; hf++) {
        int y = yy_[hf], x = xx_[hf], b = b_[hf], pix = pix_[hf];
#pragma unroll
        for (int k = 0; k < 9; k++) {
            float offy, offx;
            unpk2(offy, offx, acc[hf][k]);
            offy += __ldg(ob + 2 * k);
            offx += __ldg(ob + 2 * k + 1);
            float py = (float)(y - 1 + k / 3) + offy;
            float px = (float)(x - 1 + k % 3) + offx;
            float fy = floorf(py), fx = floorf(px);
            int y0 = (int)fy, x0 = (int)fx;
            float dy = py - fy, dx = px - fx;
            float wv[4];
#pragma unroll
            for (int t = 0; t < 4; t++) {
                int yt = y0 + (t >> 1);
                int xt = x0 + (t & 1);
                float wt = ((t >> 1) ? dy : (1.f - dy)) * ((t & 1) ? dx : (1.f - dx));
                bool valid = (yt >= 0) && (yt < Hh) && (xt >= 0) && (xt < Ww);
                wv[t] = valid ? wt : 0.f;
            }
            int y0c = y0 < -1 ? -1 : (y0 > Hh ? Hh : y0);
            int x0c = x0 < -1 ? -1 : (x0 > Ww ? Ww : x0);
            int e0 = y0c * Ww + x0c;
            int mo = (b * 9 + k) * HW + pix;
            mw[mo] = make_float4(wv[0], wv[1], wv[2], wv[3]);
            me[mo] = e0;
        }
    }
}

// ---------------------------------------------------------------------------
// Kernel 3: weight prep -> fp16 B tiles, XOR-swizzled [n][k] layout
// ---------------------------------------------------------------------------
__global__ void wprep_kernel(const float* __restrict__ dw,
                             __half* __restrict__ wh) {
    int i = blockIdx.x * blockDim.x + threadIdx.x;
    if (i >= NCH * 64 * 64) return;
    int c  = i & 63;
    int o  = (i >> 6) & 63;
    int ch = i >> 12;
    int k  = ch / 3;
    int cg = (ch % 3) * 64 + c;
    float v = __ldg(dw + o * (CIN3 * 9) + cg * 9 + k);
    int elem = o * 64 + (((c >> 3) ^ (o & 7)) << 3) + (c & 7);
    wh[ch * 4096 + elem] = __float2half_rn(v);
}

// ---------------------------------------------------------------------------
// Kernel 4: deformable conv (exact R10 config: 256 thr, 8 warps, warp tile
// 32x32, M128 x N64, double-buffered, paired-tap fp16 gather).
// Per buffer (24KB): A@0 16K | B@16K 8K
// ---------------------------------------------------------------------------
#define SM_BUF   24576
#define SM_AHOF  0
#define SM_BHOF  16384
#define SM_TOTAL (2 * SM_BUF)

__global__ __launch_bounds__(256, 2) void deform_kernel(
        const __half* __restrict__ xn, const __half* __restrict__ xs,
        const float4* __restrict__ mw, const int* __restrict__ me,
        const __half* __restrict__ wh,
        const float* __restrict__ db, float* __restrict__ out) {
    extern __shared__ char smem[];
    uint32_t sb = smem_to_u32(smem);

    int tid  = threadIdx.x;
    int lane = tid & 31;
    int warp = tid >> 5;
    int b    = blockIdx.x / 72;
    int pix0 = (blockIdx.x % 72) * 128;

    int p     = tid & 127;
    int chalf = tid >> 7;
    uint32_t a_sts = (uint32_t)p * 128;

    int m0 = (warp & 3) * 32;
    int n0 = (warp >> 2) * 32;

    float acc[2][4][4];
#pragma unroll
    for (int i = 0; i < 2; i++)
#pragma unroll
        for (int j = 0; j < 4; j++)
#pragma unroll
            for (int q = 0; q < 4; q++) acc[i][j][q] = 0.f;

    uint32_t a_m  = lane & 15;
    uint32_t a_kc = lane >> 4;
    uint32_t b_n  = ((lane >> 4) << 3) + (lane & 7);
    uint32_t b_kc = (lane >> 3) & 1;

    int bcp0 = tid;

    auto build_q = [&](int ch, int q, __half2 wtop, __half2 wbot,
                       const __half2* srcp) {
        char* bufc = smem + (ch & 1) * SM_BUF;
        __half v[8];
#pragma unroll
        for (int j = 0; j < 8; j++) {
            const __half2* pl = srcp + (q * 8 + j) * (HW / 2);
            __half2 a  = __ldg(pl);
            __half2 bb = __ldg(pl + (Ww / 2));
            __half2 t  = __hfma2(wbot, bb, __hmul2(wtop, a));
            v[j] = __hadd(__low2half(t), __high2half(t));
        }
        uint32_t hp[4];
#pragma unroll
        for (int jj = 0; jj < 4; jj++) {
            __half2 hb = __halves2half2(v[2 * jj], v[2 * jj + 1]);
            hp[jj] = *(uint32_t*)&hb;
        }
        int kc = chalf * 4 + q;
        uint32_t off = a_sts + (uint32_t)((kc ^ (p & 7)) << 4);
        *(uint4*)(bufc + SM_AHOF + off) = make_uint4(hp[0], hp[1], hp[2], hp[3]);
    };

    auto chunk_meta = [&](int ch, __half2& wtop, __half2& wbot,
                          const __half2*& srcp) {
        int k   = ch / 3;
        int cbl = ch - 3 * k;
        float4 w = __ldg(mw + (b * 9 + k) * HW + pix0 + p);
        int   e0 = __ldg(me + (b * 9 + k) * HW + pix0 + p);
        wtop = __floats2half2_rn(w.x, w.y);
        wbot = __floats2half2_rn(w.z, w.w);
        int sel = e0 & 1;
        int h2base = (e0 - sel) >> 1;
        const __half* base = sel ? xs : xn;
        srcp = (const __half2*)base
             + (size_t)(b * CIN3 + cbl * 64 + chalf * 32) * (HW / 2)
             + h2base;
    };

    auto stage_B = [&](int ch) {
        uint32_t bufb = sb + (ch & 1) * SM_BUF;
        const char* gh = (const char*)(wh + ch * 4096);
        cp_async16(bufb + SM_BHOF + bcp0 * 16, gh + bcp0 * 16);
        cp_async16(bufb + SM_BHOF + (bcp0 + 256) * 16, gh + (bcp0 + 256) * 16);
        CP_COMMIT();
    };

    // prologue: chunk 0
    stage_B(0);
    {
        __half2 wtop, wbot; const __half2* srcp;
        chunk_meta(0, wtop, wbot, srcp);
#pragma unroll
        for (int q = 0; q < 4; q++) build_q(0, q, wtop, wbot, srcp);
    }
    CP_WAIT0();
    __syncthreads();

    for (int ch = 0; ch < NCH; ch++) {
        int nxt = ch + 1;
        bool has_nxt = (nxt < NCH);
        if (has_nxt) stage_B(nxt);

        __half2 nwt = __float2half2_rn(0.f), nwb = __float2half2_rn(0.f);
        const __half2* nsrc = (const __half2*)xn;
        if (has_nxt) chunk_meta(nxt, nwt, nwb, nsrc);

        uint32_t bufb = sb + (ch & 1) * SM_BUF;
#pragma unroll
        for (int ks = 0; ks < 4; ks++) {
            uint32_t ah[2][4], bh[2][4];
#pragma unroll
            for (int mi_ = 0; mi_ < 2; mi_++) {
                uint32_t row = m0 + mi_ * 16 + a_m;
                uint32_t aoff = row * 128 + ((((ks << 1) + a_kc) ^ (row & 7)) << 4);
                ldsm_x4(ah[mi_], bufb + SM_AHOF + aoff);
            }
#pragma unroll
            for (int g = 0; g < 2; g++) {
                uint32_t n  = n0 + g * 16 + b_n;
                uint32_t kc = (ks << 1) + b_kc;
                uint32_t boff = n * 128 + ((kc ^ (n & 7)) << 4);
                ldsm_x4(bh[g], bufb + SM_BHOF + boff);
            }
#pragma unroll
            for (int mi_ = 0; mi_ < 2; mi_++)
#pragma unroll
                for (int g = 0; g < 2; g++)
#pragma unroll
                    for (int s2 = 0; s2 < 2; s2++) {
                        int ni = g * 2 + s2;
                        mma_f16(acc[mi_][ni], ah[mi_], bh[g][2 * s2], bh[g][2 * s2 + 1]);
                    }
            if (has_nxt) build_q(nxt, ks, nwt, nwb, nsrc);
        }

        CP_WAIT0();
        __syncthreads();
    }

    // epilogue: bias + relu
    int r  = lane >> 2;
    int cp = (lane & 3) * 2;
#pragma unroll
    for (int mi_ = 0; mi_ < 2; mi_++) {
        int pixb = pix0 + m0 + mi_ * 16 + r;
#pragma unroll
        for (int ni = 0; ni < 4; ni++) {
            int o = n0 + ni * 8 + cp;
            float b0v = __ldg(db + o);
            float b1v = __ldg(db + o + 1);
            float* o0 = out + (size_t)(b * Oo + o) * HW;
            float* o1 = out + (size_t)(b * Oo + o + 1) * HW;
            float v;
            v = acc[mi_][ni][0] + b0v; o0[pixb]     = v > 0.f ? v : 0.f;
            v = acc[mi_][ni][1] + b1v; o1[pixb]     = v > 0.f ? v : 0.f;
            v = acc[mi_][ni][2] + b0v; o0[pixb + 8] = v > 0.f ? v : 0.f;
            v = acc[mi_][ni][3] + b1v; o1[pixb + 8] = v > 0.f ? v : 0.f;
        }
    }
}

// ---------------------------------------------------------------------------
extern "C" void kernel_launch(void* const* d_in, const int* in_sizes, int n_in,
                              void* d_out, int out_size) {
    const float* ref  = (const float*)d_in[0];
    const float* dist = (const float*)d_in[1];
    const float* ow   = (const float*)d_in[2];
    const float* ob   = (const float*)d_in[3];
    const float* dw   = (const float*)d_in[4];
    const float* db   = (const float*)d_in[5];
    float* out = (float*)d_out;
    float* out_feat = out;
    float* out_diff = out + Bb * IMG;

    float4* mw;  cudaGetSymbolAddress((void**)&mw, g_mw);
    int*    me;  cudaGetSymbolAddress((void**)&me, g_me);
    __half* xnr; cudaGetSymbolAddress((void**)&xnr, g_xn_raw);
    __half* xsr; cudaGetSymbolAddress((void**)&xsr, g_xs_raw);
    __half* wh;  cudaGetSymbolAddress((void**)&wh, g_wh);
    __half* xn = xnr + XPAD;
    __half* xs = xsr + XPAD;

    cudaFuncSetAttribute(deform_kernel,
                         cudaFuncAttributeMaxDynamicSharedMemorySize, SM_TOTAL);

    repack_kernel<<<(NTOT + 255) / 256, 256>>>(ref, dist, out_diff, xn, xs);
    offset_meta_kernel<<<NPIX / 256, 128>>>(ref, ow, ob, mw, me);
    wprep_kernel<<<(NCH * 64 * 64 + 255) / 256, 256>>>(dw, wh);
    deform_kernel<<<NPIX / 128, 256, SM_TOTAL>>>(xn, xs, mw, me, wh, db, out_feat);
}

// round 15
// speedup vs baseline: 1.2810x; 1.1034x over previous
#include <cuda_runtime.h>
#include <cuda_fp16.h>
#include <math.h>
#include <stdint.h>

// Problem constants
#define Bb   4
#define Cc   64
#define Hh   96
#define Ww   96
#define HW   (Hh*Ww)            // 9216
#define Oo   64
#define CIN3 (3*Cc)             // 192
#define IMG  (Cc*HW)            // 589824
#define NPIX (Bb*HW)            // 36864
#define NCH  27                 // K chunks of 64: K = k*192 + c (k-major)
#define NTOT (Bb*CIN3*HW)       // 7077888
#define XPAD 256

// Scratch
__device__ float4 g_mw[Bb * 9 * HW];
__device__ int    g_me[Bb * 9 * HW];
__device__ __half g_xn_raw[NTOT + 2 * XPAD];
__device__ __half g_xs_raw[NTOT + 2 * XPAD];
__device__ __half g_wh[NCH * 64 * 64];

// ---------------- helpers ----------------
__device__ __forceinline__ uint32_t smem_to_u32(const void* p) {
    uint32_t a;
    asm("{ .reg .u64 t; cvta.to.shared.u64 t, %1; cvt.u32.u64 %0, t; }"
        : "=r"(a) : "l"(p));
    return a;
}
__device__ __forceinline__ void ldsm_x4(uint32_t* r, uint32_t addr) {
    asm volatile("ldmatrix.sync.aligned.m8n8.x4.shared.b16 {%0,%1,%2,%3}, [%4];"
        : "=r"(r[0]), "=r"(r[1]), "=r"(r[2]), "=r"(r[3]) : "r"(addr));
}
__device__ __forceinline__ void mma_f16(float* d, const uint32_t* a,
                                        uint32_t b0, uint32_t b1) {
    asm volatile("mma.sync.aligned.m16n8k16.row.col.f32.f16.f16.f32 "
        "{%0,%1,%2,%3}, {%4,%5,%6,%7}, {%8,%9}, {%0,%1,%2,%3};"
        : "+f"(d[0]), "+f"(d[1]), "+f"(d[2]), "+f"(d[3])
        : "r"(a[0]), "r"(a[1]), "r"(a[2]), "r"(a[3]), "r"(b0), "r"(b1));
}
__device__ __forceinline__ void cp_async16(uint32_t smem_addr, const void* gptr) {
    asm volatile("cp.async.cg.shared.global [%0], [%1], 16;"
        :: "r"(smem_addr), "l"(gptr));
}
#define CP_COMMIT() asm volatile("cp.async.commit_group;" ::: "memory")
#define CP_WAIT0()  asm volatile("cp.async.wait_group 0;" ::: "memory")

// packed f32x2 FMA (IEEE fp32 per lane)
__device__ __forceinline__ void ffma2(unsigned long long& c,
                                      unsigned long long a,
                                      unsigned long long b) {
    asm("fma.rn.f32x2 %0, %1, %2, %0;" : "+l"(c) : "l"(a), "l"(b));
}
__device__ __forceinline__ unsigned long long dup2(float x) {
    unsigned long long d;
    asm("mov.b64 %0, {%1, %1};" : "=l"(d) : "r"(__float_as_uint(x)));
    return d;
}
__device__ __forceinline__ void unpk2(float& lo, float& hi, unsigned long long v) {
    unsigned int l, h;
    asm("mov.b64 {%0, %1}, %2;" : "=r"(l), "=r"(h) : "l"(v));
    lo = __uint_as_float(l); hi = __uint_as_float(h);
}

// ---------------------------------------------------------------------------
// Kernel 1: diff + fp16 NCHW repack, 2 elems/thread (half2-vectorized)
// ---------------------------------------------------------------------------
__global__ void repack_kernel(const float* __restrict__ ref,
                              const float* __restrict__ dist,
                              float* __restrict__ out_diff,
                              __half* __restrict__ xn,
                              __half* __restrict__ xs) {
    int i2 = blockIdx.x * blockDim.x + threadIdx.x;
    if (i2 >= NTOT / 2) return;
    int i = i2 * 2;
    int b = i / (CIN3 * HW);
    int r = i - b * (CIN3 * HW);
    int c = r / HW;
    int e = r - c * HW;     // even; e+1 in same plane (HW even)
    float2 v2;
    if (c < Cc) {
        v2 = __ldg((const float2*)(ref + (b * Cc + c) * HW + e));
    } else if (c < 2 * Cc) {
        v2 = __ldg((const float2*)(dist + (b * Cc + (c - Cc)) * HW + e));
    } else {
        int cc = c - 2 * Cc;
        float2 rr = __ldg((const float2*)(ref  + (b * Cc + cc) * HW + e));
        float2 dd = __ldg((const float2*)(dist + (b * Cc + cc) * HW + e));
        v2.x = (rr.x - dd.x) * (rr.x - dd.x);
        v2.y = (rr.y - dd.y) * (rr.y - dd.y);
        *(float2*)(out_diff + (b * Cc + cc) * HW + e) = v2;
    }
    __half2 h2 = __float22half2_rn(v2);
    *((__half2*)xn + i2) = h2;
    if (i > 0) xs[i - 1] = __low2half(h2);
    xs[i] = __high2half(h2);
}

// ---------------------------------------------------------------------------
// Kernel 2: offset conv3x3 + bilinear meta. 288 blocks x 256 thr.
// 128 px/block; 2 threads per pixel split 64 channels (half = tid>>7).
// f32x2 packed FMA; cross-half reduction through smem float2.
// dyn smem: s_w[576*20] (46080 B) | s_red[128*9] float2 (9216 B) = 55296 B
// ---------------------------------------------------------------------------
#define OM_SMEM (46080 * 4 / 4 + 9216)   // bytes: 46080 + 9216 = 55296
__global__ __launch_bounds__(256) void offset_meta_kernel(
        const float* __restrict__ ref,
        const float* __restrict__ ow, const float* __restrict__ ob,
        float4* __restrict__ mw, int* __restrict__ me) {
    extern __shared__ __align__(16) float smem_f[];
    float*  s_w   = smem_f;
    float2* s_red = (float2*)(smem_f + 576 * 20);

    int tid = threadIdx.x;
    for (int i = tid; i < 18 * 576; i += 256) {
        int o = i / 576, ck = i % 576;
        s_w[ck * 20 + o] = ow[i];
    }
    __syncthreads();

    int lp   = tid & 127;             // local pixel
    int half = tid >> 7;              // channel half
    int p = blockIdx.x * 128 + lp;
    int b = p / HW;
    int pix = p % HW;
    int y = pix / Ww, x = pix % Ww;

    int  idx9[9]; bool ok9[9];
#pragma unroll
    for (int ky = 0; ky < 3; ky++)
#pragma unroll
        for (int kx = 0; kx < 3; kx++) {
            int yt = y + ky - 1, xt = x + kx - 1;
            bool ok = (yt >= 0) && (yt < Hh) && (xt >= 0) && (xt < Ww);
            ok9[ky * 3 + kx] = ok;
            idx9[ky * 3 + kx] = (ok ? yt : 0) * Ww + (ok ? xt : 0);
        }

    unsigned long long acc[9];
#pragma unroll
    for (int j = 0; j < 9; j++) acc[j] = 0ull;

    const float* xb = ref + b * IMG + half * 32 * HW;
    for (int cj = 0; cj < 32; cj++) {
        int c = half * 32 + cj;
        const float* xc = xb + cj * HW;
#pragma unroll
        for (int k = 0; k < 9; k++) {
            float v = ok9[k] ? __ldg(xc + idx9[k]) : 0.f;
            unsigned long long d = dup2(v);
            const unsigned long long* wp =
                (const unsigned long long*)&s_w[(c * 9 + k) * 20];
            ffma2(acc[0], d, wp[0]);
            ffma2(acc[1], d, wp[1]);
            ffma2(acc[2], d, wp[2]);
            ffma2(acc[3], d, wp[3]);
            ffma2(acc[4], d, wp[4]);
            ffma2(acc[5], d, wp[5]);
            ffma2(acc[6], d, wp[6]);
            ffma2(acc[7], d, wp[7]);
            ffma2(acc[8], d, wp[8]);
        }
    }

    // cross-half reduction
    if (half == 1) {
#pragma unroll
        for (int j = 0; j < 9; j++) {
            float lo, hi; unpk2(lo, hi, acc[j]);
            s_red[lp * 9 + j] = make_float2(lo, hi);
        }
    }
    __syncthreads();
    if (half == 0) {
#pragma unroll
        for (int k = 0; k < 9; k++) {
            float offy, offx;
            unpk2(offy, offx, acc[k]);
            float2 r2 = s_red[lp * 9 + k];
            offy += r2.x + __ldg(ob + 2 * k);
            offx += r2.y + __ldg(ob + 2 * k + 1);
            float py = (float)(y - 1 + k / 3) + offy;
            float px = (float)(x - 1 + k % 3) + offx;
            float fy = floorf(py), fx = floorf(px);
            int y0 = (int)fy, x0 = (int)fx;
            float dy = py - fy, dx = px - fx;
            float wv[4];
#pragma unroll
            for (int t = 0; t < 4; t++) {
                int yt = y0 + (t >> 1);
                int xt = x0 + (t & 1);
                float wt = ((t >> 1) ? dy : (1.f - dy)) * ((t & 1) ? dx : (1.f - dx));
                bool valid = (yt >= 0) && (yt < Hh) && (xt >= 0) && (xt < Ww);
                wv[t] = valid ? wt : 0.f;
            }
            int y0c = y0 < -1 ? -1 : (y0 > Hh ? Hh : y0);
            int x0c = x0 < -1 ? -1 : (x0 > Ww ? Ww : x0);
            int e0 = y0c * Ww + x0c;
            int mo = (b * 9 + k) * HW + pix;
            mw[mo] = make_float4(wv[0], wv[1], wv[2], wv[3]);
            me[mo] = e0;
        }
    }
}

// ---------------------------------------------------------------------------
// Kernel 3: weight prep -> fp16 B tiles, XOR-swizzled [n][k] layout
// ---------------------------------------------------------------------------
__global__ void wprep_kernel(const float* __restrict__ dw,
                             __half* __restrict__ wh) {
    int i = blockIdx.x * blockDim.x + threadIdx.x;
    if (i >= NCH * 64 * 64) return;
    int c  = i & 63;
    int o  = (i >> 6) & 63;
    int ch = i >> 12;
    int k  = ch / 3;
    int cg = (ch % 3) * 64 + c;
    float v = __ldg(dw + o * (CIN3 * 9) + cg * 9 + k);
    int elem = o * 64 + (((c >> 3) ^ (o & 7)) << 3) + (c & 7);
    wh[ch * 4096 + elem] = __float2half_rn(v);
}

// ---------------------------------------------------------------------------
// Kernel 4: deformable conv (R10/R14 config, unchanged: 256 thr, warp tile
// 32x32, M128 x N64, double-buffered, paired-tap fp16 gather).
// Per buffer (24KB): A@0 16K | B@16K 8K
// ---------------------------------------------------------------------------
#define SM_BUF   24576
#define SM_AHOF  0
#define SM_BHOF  16384
#define SM_TOTAL (2 * SM_BUF)

__global__ __launch_bounds__(256, 2) void deform_kernel(
        const __half* __restrict__ xn, const __half* __restrict__ xs,
        const float4* __restrict__ mw, const int* __restrict__ me,
        const __half* __restrict__ wh,
        const float* __restrict__ db, float* __restrict__ out) {
    extern __shared__ char smem[];
    uint32_t sb = smem_to_u32(smem);

    int tid  = threadIdx.x;
    int lane = tid & 31;
    int warp = tid >> 5;
    int b    = blockIdx.x / 72;
    int pix0 = (blockIdx.x % 72) * 128;

    int p     = tid & 127;
    int chalf = tid >> 7;
    uint32_t a_sts = (uint32_t)p * 128;

    int m0 = (warp & 3) * 32;
    int n0 = (warp >> 2) * 32;

    float acc[2][4][4];
#pragma unroll
    for (int i = 0; i < 2; i++)
#pragma unroll
        for (int j = 0; j < 4; j++)
#pragma unroll
            for (int q = 0; q < 4; q++) acc[i][j][q] = 0.f;

    uint32_t a_m  = lane & 15;
    uint32_t a_kc = lane >> 4;
    uint32_t b_n  = ((lane >> 4) << 3) + (lane & 7);
    uint32_t b_kc = (lane >> 3) & 1;

    int bcp0 = tid;

    auto build_q = [&](int ch, int q, __half2 wtop, __half2 wbot,
                       const __half2* srcp) {
        char* bufc = smem + (ch & 1) * SM_BUF;
        __half v[8];
#pragma unroll
        for (int j = 0; j < 8; j++) {
            const __half2* pl = srcp + (q * 8 + j) * (HW / 2);
            __half2 a  = __ldg(pl);
            __half2 bb = __ldg(pl + (Ww / 2));
            __half2 t  = __hfma2(wbot, bb, __hmul2(wtop, a));
            v[j] = __hadd(__low2half(t), __high2half(t));
        }
        uint32_t hp[4];
#pragma unroll
        for (int jj = 0; jj < 4; jj++) {
            __half2 hb = __halves2half2(v[2 * jj], v[2 * jj + 1]);
            hp[jj] = *(uint32_t*)&hb;
        }
        int kc = chalf * 4 + q;
        uint32_t off = a_sts + (uint32_t)((kc ^ (p & 7)) << 4);
        *(uint4*)(bufc + SM_AHOF + off) = make_uint4(hp[0], hp[1], hp[2], hp[3]);
    };

    auto chunk_meta = [&](int ch, __half2& wtop, __half2& wbot,
                          const __half2*& srcp) {
        int k   = ch / 3;
        int cbl = ch - 3 * k;
        float4 w = __ldg(mw + (b * 9 + k) * HW + pix0 + p);
        int   e0 = __ldg(me + (b * 9 + k) * HW + pix0 + p);
        wtop = __floats2half2_rn(w.x, w.y);
        wbot = __floats2half2_rn(w.z, w.w);
        int sel = e0 & 1;
        int h2base = (e0 - sel) >> 1;
        const __half* base = sel ? xs : xn;
        srcp = (const __half2*)base
             + (size_t)(b * CIN3 + cbl * 64 + chalf * 32) * (HW / 2)
             + h2base;
    };

    auto stage_B = [&](int ch) {
        uint32_t bufb = sb + (ch & 1) * SM_BUF;
        const char* gh = (const char*)(wh + ch * 4096);
        cp_async16(bufb + SM_BHOF + bcp0 * 16, gh + bcp0 * 16);
        cp_async16(bufb + SM_BHOF + (bcp0 + 256) * 16, gh + (bcp0 + 256) * 16);
        CP_COMMIT();
    };

    // prologue: chunk 0
    stage_B(0);
    {
        __half2 wtop, wbot; const __half2* srcp;
        chunk_meta(0, wtop, wbot, srcp);
#pragma unroll
        for (int q = 0; q < 4; q++) build_q(0, q, wtop, wbot, srcp);
    }
    CP_WAIT0();
    __syncthreads();

    for (int ch = 0; ch < NCH; ch++) {
        int nxt = ch + 1;
        bool has_nxt = (nxt < NCH);
        if (has_nxt) stage_B(nxt);

        __half2 nwt = __float2half2_rn(0.f), nwb = __float2half2_rn(0.f);
        const __half2* nsrc = (const __half2*)xn;
        if (has_nxt) chunk_meta(nxt, nwt, nwb, nsrc);

        uint32_t bufb = sb + (ch & 1) * SM_BUF;
#pragma unroll
        for (int ks = 0; ks < 4; ks++) {
            uint32_t ah[2][4], bh[2][4];
#pragma unroll
            for (int mi_ = 0; mi_ < 2; mi_++) {
                uint32_t row = m0 + mi_ * 16 + a_m;
                uint32_t aoff = row * 128 + ((((ks << 1) + a_kc) ^ (row & 7)) << 4);
                ldsm_x4(ah[mi_], bufb + SM_AHOF + aoff);
            }
#pragma unroll
            for (int g = 0; g < 2; g++) {
                uint32_t n  = n0 + g * 16 + b_n;
                uint32_t kc = (ks << 1) + b_kc;
                uint32_t boff = n * 128 + ((kc ^ (n & 7)) << 4);
                ldsm_x4(bh[g], bufb + SM_BHOF + boff);
            }
#pragma unroll
            for (int mi_ = 0; mi_ < 2; mi_++)
#pragma unroll
                for (int g = 0; g < 2; g++)
#pragma unroll
                    for (int s2 = 0; s2 < 2; s2++) {
                        int ni = g * 2 + s2;
                        mma_f16(acc[mi_][ni], ah[mi_], bh[g][2 * s2], bh[g][2 * s2 + 1]);
                    }
            if (has_nxt) build_q(nxt, ks, nwt, nwb, nsrc);
        }

        CP_WAIT0();
        __syncthreads();
    }

    // epilogue: bias + relu
    int r  = lane >> 2;
    int cp = (lane & 3) * 2;
#pragma unroll
    for (int mi_ = 0; mi_ < 2; mi_++) {
        int pixb = pix0 + m0 + mi_ * 16 + r;
#pragma unroll
        for (int ni = 0; ni < 4; ni++) {
            int o = n0 + ni * 8 + cp;
            float b0v = __ldg(db + o);
            float b1v = __ldg(db + o + 1);
            float* o0 = out + (size_t)(b * Oo + o) * HW;
            float* o1 = out + (size_t)(b * Oo + o + 1) * HW;
            float v;
            v = acc[mi_][ni][0] + b0v; o0[pixb]     = v > 0.f ? v : 0.f;
            v = acc[mi_][ni][1] + b1v; o1[pixb]     = v > 0.f ? v : 0.f;
            v = acc[mi_][ni][2] + b0v; o0[pixb + 8] = v > 0.f ? v : 0.f;
            v = acc[mi_][ni][3] + b1v; o1[pixb + 8] = v > 0.f ? v : 0.f;
        }
    }
}

// ---------------------------------------------------------------------------
extern "C" void kernel_launch(void* const* d_in, const int* in_sizes, int n_in,
                              void* d_out, int out_size) {
    const float* ref  = (const float*)d_in[0];
    const float* dist = (const float*)d_in[1];
    const float* ow   = (const float*)d_in[2];
    const float* ob   = (const float*)d_in[3];
    const float* dw   = (const float*)d_in[4];
    const float* db   = (const float*)d_in[5];
    float* out = (float*)d_out;
    float* out_feat = out;
    float* out_diff = out + Bb * IMG;

    float4* mw;  cudaGetSymbolAddress((void**)&mw, g_mw);
    int*    me;  cudaGetSymbolAddress((void**)&me, g_me);
    __half* xnr; cudaGetSymbolAddress((void**)&xnr, g_xn_raw);
    __half* xsr; cudaGetSymbolAddress((void**)&xsr, g_xs_raw);
    __half* wh;  cudaGetSymbolAddress((void**)&wh, g_wh);
    __half* xn = xnr + XPAD;
    __half* xs = xsr + XPAD;

    cudaFuncSetAttribute(deform_kernel,
                         cudaFuncAttributeMaxDynamicSharedMemorySize, SM_TOTAL);
    cudaFuncSetAttribute(offset_meta_kernel,
                         cudaFuncAttributeMaxDynamicSharedMemorySize, 55296);

    repack_kernel<<<(NTOT / 2 + 255) / 256, 256>>>(ref, dist, out_diff, xn, xs);
    offset_meta_kernel<<<288, 256, 55296>>>(ref, ow, ob, mw, me);
    wprep_kernel<<<(NCH * 64 * 64 + 255) / 256, 256>>>(dw, wh);
    deform_kernel<<<NPIX / 128, 256, SM_TOTAL>>>(xn, xs, mw, me, wh, db, out_feat);
}